// round 2
// baseline (speedup 1.0000x reference)
#include <cuda_runtime.h>
#include <cstdint>

// GCN 2-layer fused pipeline for B200 (sm_100a)
// Layers: h = X W ; agg = scatter(norm * h[src] -> dst) + dis^2 * h ; relu
// Scratch lives in __device__ globals (allocation rules).

#define N_NODES 100000
#define N_EDGES 1600000
#define D 64

__device__ float g_dis[N_NODES];          // degree -> rsqrt(degree)
__device__ float g_norm[N_EDGES];         // dis[src]*w*dis[dst]
__device__ float g_h[N_NODES * D];        // X@W result (both layers, reused)
__device__ float g_agg[N_NODES * D];      // layer-1 aggregation

// ---------------------------------------------------------------------------
// degree / normalization prep
// ---------------------------------------------------------------------------
__global__ void k_init_deg() {
    int i = blockIdx.x * blockDim.x + threadIdx.x;
    if (i < N_NODES) g_dis[i] = 1.0f;   // self-loop weight 1
}

__global__ void k_deg(const int* __restrict__ dst,
                      const float* __restrict__ w) {
    int e = blockIdx.x * blockDim.x + threadIdx.x;
    if (e >= N_EDGES) return;
    atomicAdd(&g_dis[dst[e]], w[e]);
}

__global__ void k_rsqrt() {
    int i = blockIdx.x * blockDim.x + threadIdx.x;
    if (i < N_NODES) g_dis[i] = rsqrtf(g_dis[i]);
}

__global__ void k_norm(const int* __restrict__ src,
                       const int* __restrict__ dst,
                       const float* __restrict__ w) {
    int e = blockIdx.x * blockDim.x + threadIdx.x;
    if (e >= N_EDGES) return;
    g_norm[e] = g_dis[src[e]] * w[e] * g_dis[dst[e]];
}

// ---------------------------------------------------------------------------
// dense 64x64 GEMM: H[row] = act(X[row]) @ W  (act = relu if relu_in)
// one thread per node row; W staged in smem; float4 smem loads.
// ---------------------------------------------------------------------------
__global__ void __launch_bounds__(128) k_gemm(const float* __restrict__ X,
                                              const float* __restrict__ W,
                                              float* __restrict__ H,
                                              int relu_in) {
    __shared__ float Ws[D * D];
    int tid = threadIdx.x;
    {   // cooperative load of W (4096 floats = 1024 float4)
        const float4* W4 = (const float4*)W;
        float4* Ws4 = (float4*)Ws;
#pragma unroll
        for (int i = 0; i < 8; ++i) Ws4[tid + i * 128] = W4[tid + i * 128];
    }
    __syncthreads();

    int row = blockIdx.x * 128 + tid;
    if (row >= N_NODES) return;

    const float4* x4 = (const float4*)(X + (size_t)row * D);

#pragma unroll 1
    for (int jc = 0; jc < 4; ++jc) {           // 16-wide output chunks
        float acc[16];
#pragma unroll
        for (int j = 0; j < 16; ++j) acc[j] = 0.f;

#pragma unroll
        for (int k4 = 0; k4 < 16; ++k4) {      // K in groups of 4
            float4 xv = x4[k4];                 // L1-hot after first chunk
            if (relu_in) {
                xv.x = fmaxf(xv.x, 0.f); xv.y = fmaxf(xv.y, 0.f);
                xv.z = fmaxf(xv.z, 0.f); xv.w = fmaxf(xv.w, 0.f);
            }
            float xs[4] = {xv.x, xv.y, xv.z, xv.w};
#pragma unroll
            for (int kk = 0; kk < 4; ++kk) {
                int k = k4 * 4 + kk;
                const float4* wrow = (const float4*)(Ws + k * D + jc * 16);
#pragma unroll
                for (int q = 0; q < 4; ++q) {
                    float4 wv = wrow[q];        // broadcast LDS.128
                    acc[q * 4 + 0] = fmaf(xs[kk], wv.x, acc[q * 4 + 0]);
                    acc[q * 4 + 1] = fmaf(xs[kk], wv.y, acc[q * 4 + 1]);
                    acc[q * 4 + 2] = fmaf(xs[kk], wv.z, acc[q * 4 + 2]);
                    acc[q * 4 + 3] = fmaf(xs[kk], wv.w, acc[q * 4 + 3]);
                }
            }
        }
        float4* out4 = (float4*)(H + (size_t)row * D + jc * 16);
#pragma unroll
        for (int q = 0; q < 4; ++q)
            out4[q] = make_float4(acc[q * 4 + 0], acc[q * 4 + 1],
                                  acc[q * 4 + 2], acc[q * 4 + 3]);
    }
}

// ---------------------------------------------------------------------------
// self-loop init: A[i] = dis[i]^2 * H[i]  (also initializes the output buffer)
// one float4 per thread
// ---------------------------------------------------------------------------
__global__ void k_self(const float* __restrict__ H, float* __restrict__ A) {
    int idx = blockIdx.x * blockDim.x + threadIdx.x;
    if (idx >= N_NODES * 16) return;
    int node = idx >> 4;
    float di = g_dis[node];
    di *= di;
    float4 v = ((const float4*)H)[idx];
    v.x *= di; v.y *= di; v.z *= di; v.w *= di;
    ((float4*)A)[idx] = v;
}

// ---------------------------------------------------------------------------
// edge scatter: 16 threads per edge, each handles one float4 of the 64-float
// row. Gather from h[src] is fully coalesced (256B/edge); scatter uses
// red.global.add.v4.f32 (no-return vector reduction) to coalesced addresses.
// ---------------------------------------------------------------------------
__global__ void __launch_bounds__(256) k_scatter(const int* __restrict__ src,
                                                 const int* __restrict__ dst,
                                                 const float* __restrict__ H,
                                                 float* __restrict__ A) {
    int idx = blockIdx.x * 256 + threadIdx.x;
    int e = idx >> 4;
    if (e >= N_EDGES) return;
    int l = idx & 15;
    int s = src[e];
    int d = dst[e];
    float nm = g_norm[e];
    float4 v = ((const float4*)H)[s * 16 + l];
    float* p = A + (size_t)d * D + l * 4;
    asm volatile("red.global.add.v4.f32 [%0], {%1, %2, %3, %4};"
                 :: "l"(p), "f"(v.x * nm), "f"(v.y * nm),
                    "f"(v.z * nm), "f"(v.w * nm)
                 : "memory");
}

// ---------------------------------------------------------------------------
// final relu on output
// ---------------------------------------------------------------------------
__global__ void k_relu(float* __restrict__ A) {
    int idx = blockIdx.x * blockDim.x + threadIdx.x;
    if (idx >= N_NODES * 16) return;
    float4 v = ((float4*)A)[idx];
    v.x = fmaxf(v.x, 0.f); v.y = fmaxf(v.y, 0.f);
    v.z = fmaxf(v.z, 0.f); v.w = fmaxf(v.w, 0.f);
    ((float4*)A)[idx] = v;
}

// ---------------------------------------------------------------------------
extern "C" void kernel_launch(void* const* d_in, const int* in_sizes, int n_in,
                              void* d_out, int out_size) {
    const float* x   = (const float*)d_in[0];
    const int*   ei  = (const int*)d_in[1];     // int32: JAX x64-disabled
    const float* w   = (const float*)d_in[2];
    const float* W0  = (const float*)d_in[3];
    const float* W1  = (const float*)d_in[4];
    float* out = (float*)d_out;

    const int* src = ei;                // row 0
    const int* dst = ei + N_EDGES;      // row 1

    float *p_h, *p_agg;
    cudaGetSymbolAddress((void**)&p_h, g_h);
    cudaGetSymbolAddress((void**)&p_agg, g_agg);

    const int TB = 256;
    int gN   = (N_NODES + TB - 1) / TB;
    int gE   = (N_EDGES + TB - 1) / TB;
    int gN16 = (N_NODES * 16 + TB - 1) / TB;
    int gE16 = (N_EDGES / 16);            // E*16/256 exactly
    int gGemm = (N_NODES + 127) / 128;

    // normalization prep
    k_init_deg<<<gN, TB>>>();
    k_deg<<<gE, TB>>>(dst, w);
    k_rsqrt<<<gN, TB>>>();
    k_norm<<<gE, TB>>>(src, dst, w);

    // layer 1
    k_gemm<<<gGemm, 128>>>(x, W0, p_h, 0);
    k_self<<<gN16, TB>>>(p_h, p_agg);
    k_scatter<<<gE16, TB>>>(src, dst, p_h, p_agg);

    // layer 2 (relu of layer-1 folded into gemm load; output agg lives in d_out)
    k_gemm<<<gGemm, 128>>>(p_agg, W1, p_h, 1);
    k_self<<<gN16, TB>>>(p_h, out);
    k_scatter<<<gE16, TB>>>(src, dst, p_h, out);
    k_relu<<<gN16, TB>>>(out);
}

// round 3
// speedup vs baseline: 1.0064x; 1.0064x over previous
#include <cuda_runtime.h>
#include <cstdint>

// GCN 2-layer fused pipeline for B200 (sm_100a)
// h = X W ; agg = dis^2*h + scatter(norm * h[src] -> dst) ; relu
// Self-loop term fused into GEMM epilogue; norm/deg prep vectorized.

#define N_NODES 100000
#define N_EDGES 1600000
#define D 64

__device__ float g_dis[N_NODES];          // degree -> rsqrt(degree)
__device__ float g_norm[N_EDGES];         // dis[src]*w*dis[dst]
__device__ float g_h[N_NODES * D];        // X@W result (both layers, reused)
__device__ float g_agg[N_NODES * D];      // layer-1 aggregation

// ---------------------------------------------------------------------------
// degree / normalization prep
// ---------------------------------------------------------------------------
__global__ void k_init_deg() {
    int i = blockIdx.x * blockDim.x + threadIdx.x;
    if (i < N_NODES) g_dis[i] = 1.0f;   // self-loop weight 1
}

// 4 edges per thread, vectorized streams
__global__ void k_deg(const int* __restrict__ dst,
                      const float* __restrict__ w) {
    int t = blockIdx.x * blockDim.x + threadIdx.x;
    if (t >= N_EDGES / 4) return;
    int4   dv = ((const int4*)dst)[t];
    float4 wv = ((const float4*)w)[t];
    atomicAdd(&g_dis[dv.x], wv.x);
    atomicAdd(&g_dis[dv.y], wv.y);
    atomicAdd(&g_dis[dv.z], wv.z);
    atomicAdd(&g_dis[dv.w], wv.w);
}

__global__ void k_rsqrt() {
    int i = blockIdx.x * blockDim.x + threadIdx.x;
    if (i < N_NODES) g_dis[i] = rsqrtf(g_dis[i]);
}

// 4 edges per thread: 8 independent dis-gathers in flight (MLP)
__global__ void k_norm(const int* __restrict__ src,
                       const int* __restrict__ dst,
                       const float* __restrict__ w) {
    int t = blockIdx.x * blockDim.x + threadIdx.x;
    if (t >= N_EDGES / 4) return;
    int4   sv = ((const int4*)src)[t];
    int4   dv = ((const int4*)dst)[t];
    float4 wv = ((const float4*)w)[t];
    float s0 = g_dis[sv.x], s1 = g_dis[sv.y], s2 = g_dis[sv.z], s3 = g_dis[sv.w];
    float d0 = g_dis[dv.x], d1 = g_dis[dv.y], d2 = g_dis[dv.z], d3 = g_dis[dv.w];
    float4 nv = make_float4(s0 * wv.x * d0, s1 * wv.y * d1,
                            s2 * wv.z * d2, s3 * wv.w * d3);
    ((float4*)g_norm)[t] = nv;
}

// ---------------------------------------------------------------------------
// dense 64x64 GEMM with fused self-loop epilogue:
//   H[row] = act(X[row]) @ W     (act = relu if relu_in)
//   A[row] = dis[row]^2 * H[row] (initializes the aggregation buffer)
// one thread per node row; W staged in smem.
// ---------------------------------------------------------------------------
__global__ void __launch_bounds__(128) k_gemm(const float* __restrict__ X,
                                              const float* __restrict__ W,
                                              float* __restrict__ H,
                                              float* __restrict__ A,
                                              int relu_in) {
    __shared__ float Ws[D * D];
    int tid = threadIdx.x;
    {   // cooperative load of W (4096 floats = 1024 float4)
        const float4* W4 = (const float4*)W;
        float4* Ws4 = (float4*)Ws;
#pragma unroll
        for (int i = 0; i < 8; ++i) Ws4[tid + i * 128] = W4[tid + i * 128];
    }
    __syncthreads();

    int row = blockIdx.x * 128 + tid;
    if (row >= N_NODES) return;

    float di = g_dis[row];
    float di2 = di * di;

    const float4* x4 = (const float4*)(X + (size_t)row * D);

#pragma unroll 1
    for (int jc = 0; jc < 4; ++jc) {           // 16-wide output chunks
        float acc[16];
#pragma unroll
        for (int j = 0; j < 16; ++j) acc[j] = 0.f;

#pragma unroll
        for (int k4 = 0; k4 < 16; ++k4) {      // K in groups of 4
            float4 xv = x4[k4];                 // L1-hot after first chunk
            if (relu_in) {
                xv.x = fmaxf(xv.x, 0.f); xv.y = fmaxf(xv.y, 0.f);
                xv.z = fmaxf(xv.z, 0.f); xv.w = fmaxf(xv.w, 0.f);
            }
            float xs[4] = {xv.x, xv.y, xv.z, xv.w};
#pragma unroll
            for (int kk = 0; kk < 4; ++kk) {
                int k = k4 * 4 + kk;
                const float4* wrow = (const float4*)(Ws + k * D + jc * 16);
#pragma unroll
                for (int q = 0; q < 4; ++q) {
                    float4 wv = wrow[q];        // broadcast LDS.128
                    acc[q * 4 + 0] = fmaf(xs[kk], wv.x, acc[q * 4 + 0]);
                    acc[q * 4 + 1] = fmaf(xs[kk], wv.y, acc[q * 4 + 1]);
                    acc[q * 4 + 2] = fmaf(xs[kk], wv.z, acc[q * 4 + 2]);
                    acc[q * 4 + 3] = fmaf(xs[kk], wv.w, acc[q * 4 + 3]);
                }
            }
        }
        float4* out4 = (float4*)(H + (size_t)row * D + jc * 16);
        float4* a4   = (float4*)(A + (size_t)row * D + jc * 16);
#pragma unroll
        for (int q = 0; q < 4; ++q) {
            out4[q] = make_float4(acc[q * 4 + 0], acc[q * 4 + 1],
                                  acc[q * 4 + 2], acc[q * 4 + 3]);
            a4[q]   = make_float4(acc[q * 4 + 0] * di2, acc[q * 4 + 1] * di2,
                                  acc[q * 4 + 2] * di2, acc[q * 4 + 3] * di2);
        }
    }
}

// ---------------------------------------------------------------------------
// edge scatter: 16 threads per edge, each handles one float4 of the 64-float
// row. Gather from h[src] is fully coalesced (256B/edge); scatter uses
// red.global.add.v4.f32 (no-return vector reduction) to coalesced addresses.
// ---------------------------------------------------------------------------
__global__ void __launch_bounds__(256) k_scatter(const int* __restrict__ src,
                                                 const int* __restrict__ dst,
                                                 const float* __restrict__ H,
                                                 float* __restrict__ A) {
    int idx = blockIdx.x * 256 + threadIdx.x;
    int e = idx >> 4;
    if (e >= N_EDGES) return;
    int l = idx & 15;
    int s = src[e];
    int d = dst[e];
    float nm = g_norm[e];
    float4 v = ((const float4*)H)[s * 16 + l];
    float* p = A + (size_t)d * D + l * 4;
    asm volatile("red.global.add.v4.f32 [%0], {%1, %2, %3, %4};"
                 :: "l"(p), "f"(v.x * nm), "f"(v.y * nm),
                    "f"(v.z * nm), "f"(v.w * nm)
                 : "memory");
}

// ---------------------------------------------------------------------------
// final relu on output
// ---------------------------------------------------------------------------
__global__ void k_relu(float* __restrict__ A) {
    int idx = blockIdx.x * blockDim.x + threadIdx.x;
    if (idx >= N_NODES * 16) return;
    float4 v = ((float4*)A)[idx];
    v.x = fmaxf(v.x, 0.f); v.y = fmaxf(v.y, 0.f);
    v.z = fmaxf(v.z, 0.f); v.w = fmaxf(v.w, 0.f);
    ((float4*)A)[idx] = v;
}

// ---------------------------------------------------------------------------
extern "C" void kernel_launch(void* const* d_in, const int* in_sizes, int n_in,
                              void* d_out, int out_size) {
    const float* x   = (const float*)d_in[0];
    const int*   ei  = (const int*)d_in[1];     // int32: JAX x64-disabled
    const float* w   = (const float*)d_in[2];
    const float* W0  = (const float*)d_in[3];
    const float* W1  = (const float*)d_in[4];
    float* out = (float*)d_out;

    const int* src = ei;                // row 0
    const int* dst = ei + N_EDGES;      // row 1

    float *p_h, *p_agg;
    cudaGetSymbolAddress((void**)&p_h, g_h);
    cudaGetSymbolAddress((void**)&p_agg, g_agg);

    const int TB = 256;
    int gN   = (N_NODES + TB - 1) / TB;
    int gE4  = (N_EDGES / 4 + TB - 1) / TB;
    int gN16 = (N_NODES * 16 + TB - 1) / TB;
    int gE16 = (N_EDGES / 16);            // E*16/256 exactly
    int gGemm = (N_NODES + 127) / 128;

    // normalization prep
    k_init_deg<<<gN, TB>>>();
    k_deg<<<gE4, TB>>>(dst, w);
    k_rsqrt<<<gN, TB>>>();
    k_norm<<<gE4, TB>>>(src, dst, w);

    // layer 1 (self-loop fused into gemm epilogue)
    k_gemm<<<gGemm, 128>>>(x, W0, p_h, p_agg, 0);
    k_scatter<<<gE16, TB>>>(src, dst, p_h, p_agg);

    // layer 2 (relu of layer-1 folded into gemm load; agg lives in d_out)
    k_gemm<<<gGemm, 128>>>(p_agg, W1, p_h, out, 1);
    k_scatter<<<gE16, TB>>>(src, dst, p_h, out);
    k_relu<<<gN16, TB>>>(out);
}

// round 4
// speedup vs baseline: 1.3453x; 1.3368x over previous
#include <cuda_runtime.h>
#include <cstdint>

// GCN 2-layer, CSR two-phase aggregation (no feature atomics), sm_100a.
// Pipeline:
//   prep:  cnt/deg histogram -> rsqrt -> scan(row_start) -> fill bins(src,norm)
//   layer: H = X@W (smem-staged 64x64 GEMM)
//          A[n] = relu( dis[n]^2*H[n] + sum_{e in bin(n)} norm_e * H[src_e] )

#define N_NODES 100000
#define N_EDGES 1600000
#define D 64
#define SCAN_BS 512
#define NB ((N_NODES + SCAN_BS - 1) / SCAN_BS)   // 196

__device__ float g_dis[N_NODES];        // rsqrt(degree)
__device__ int   g_cnt[N_NODES];        // in-degree (edges only)
__device__ int   g_row[N_NODES];        // CSR row start
__device__ int   g_cur[N_NODES];        // fill cursor
__device__ int   g_bsum[NB];            // block sums for scan
__device__ int   g_boff[NB];            // block offsets (exclusive)
__device__ int2  g_bins[N_EDGES];       // (src, norm-as-int) per edge, dst-binned
__device__ float g_h[N_NODES * D];      // X@W result (both layers)
__device__ float g_agg[N_NODES * D];    // layer-1 output

// ---------------------------------------------------------------------------
__global__ void k_init() {
    int i = blockIdx.x * blockDim.x + threadIdx.x;
    if (i < N_NODES) { g_dis[i] = 1.0f; g_cnt[i] = 0; }
}

// weighted degree + count histogram, 4 edges/thread
__global__ void k_hist(const int* __restrict__ dst,
                       const float* __restrict__ w) {
    int t = blockIdx.x * blockDim.x + threadIdx.x;
    if (t >= N_EDGES / 4) return;
    int4   dv = ((const int4*)dst)[t];
    float4 wv = ((const float4*)w)[t];
    atomicAdd(&g_dis[dv.x], wv.x);  atomicAdd(&g_cnt[dv.x], 1);
    atomicAdd(&g_dis[dv.y], wv.y);  atomicAdd(&g_cnt[dv.y], 1);
    atomicAdd(&g_dis[dv.z], wv.z);  atomicAdd(&g_cnt[dv.z], 1);
    atomicAdd(&g_dis[dv.w], wv.w);  atomicAdd(&g_cnt[dv.w], 1);
}

__global__ void k_rsqrt() {
    int i = blockIdx.x * blockDim.x + threadIdx.x;
    if (i < N_NODES) g_dis[i] = rsqrtf(g_dis[i]);
}

// scan stage 1: per-block sum of cnt
__global__ void __launch_bounds__(SCAN_BS) k_reduce() {
    __shared__ int s[SCAN_BS];
    int i = blockIdx.x * SCAN_BS + threadIdx.x;
    s[threadIdx.x] = (i < N_NODES) ? g_cnt[i] : 0;
    __syncthreads();
    for (int off = SCAN_BS / 2; off > 0; off >>= 1) {
        if (threadIdx.x < off) s[threadIdx.x] += s[threadIdx.x + off];
        __syncthreads();
    }
    if (threadIdx.x == 0) g_bsum[blockIdx.x] = s[0];
}

// scan stage 2: exclusive scan of NB block sums (single block)
__global__ void __launch_bounds__(256) k_scanp() {
    __shared__ int s[256];
    int t = threadIdx.x;
    int v = (t < NB) ? g_bsum[t] : 0;
    s[t] = v;
    __syncthreads();
    for (int off = 1; off < 256; off <<= 1) {
        int add = (t >= off) ? s[t - off] : 0;
        __syncthreads();
        s[t] += add;
        __syncthreads();
    }
    if (t < NB) g_boff[t] = s[t] - v;   // exclusive
}

// scan stage 3: local exclusive scan + block offset -> row_start, cursor
__global__ void __launch_bounds__(SCAN_BS) k_offsets() {
    __shared__ int s[SCAN_BS];
    int i = blockIdx.x * SCAN_BS + threadIdx.x;
    int t = threadIdx.x;
    int c = (i < N_NODES) ? g_cnt[i] : 0;
    s[t] = c;
    __syncthreads();
    for (int off = 1; off < SCAN_BS; off <<= 1) {
        int add = (t >= off) ? s[t - off] : 0;
        __syncthreads();
        s[t] += add;
        __syncthreads();
    }
    if (i < N_NODES) {
        int r = g_boff[blockIdx.x] + s[t] - c;   // exclusive
        g_row[i] = r;
        g_cur[i] = r;
    }
}

// fill bins: per edge compute norm inline, cursor-atomic into dst bin
__global__ void k_fill(const int* __restrict__ src,
                       const int* __restrict__ dst,
                       const float* __restrict__ w) {
    int e = blockIdx.x * blockDim.x + threadIdx.x;
    if (e >= N_EDGES) return;
    int s = src[e];
    int d = dst[e];
    float nm = g_dis[s] * w[e] * g_dis[d];
    int pos = atomicAdd(&g_cur[d], 1);
    g_bins[pos] = make_int2(s, __float_as_int(nm));
}

// ---------------------------------------------------------------------------
// dense 64x64 GEMM: H[row] = X[row] @ W ; one thread per node row
// ---------------------------------------------------------------------------
__global__ void __launch_bounds__(128) k_gemm(const float* __restrict__ X,
                                              const float* __restrict__ W,
                                              float* __restrict__ H) {
    __shared__ float Ws[D * D];
    int tid = threadIdx.x;
    {
        const float4* W4 = (const float4*)W;
        float4* Ws4 = (float4*)Ws;
#pragma unroll
        for (int i = 0; i < 8; ++i) Ws4[tid + i * 128] = W4[tid + i * 128];
    }
    __syncthreads();

    int row = blockIdx.x * 128 + tid;
    if (row >= N_NODES) return;

    const float4* x4 = (const float4*)(X + (size_t)row * D);

#pragma unroll 1
    for (int jc = 0; jc < 4; ++jc) {
        float acc[16];
#pragma unroll
        for (int j = 0; j < 16; ++j) acc[j] = 0.f;

#pragma unroll
        for (int k4 = 0; k4 < 16; ++k4) {
            float4 xv = x4[k4];
            float xs[4] = {xv.x, xv.y, xv.z, xv.w};
#pragma unroll
            for (int kk = 0; kk < 4; ++kk) {
                int k = k4 * 4 + kk;
                const float4* wrow = (const float4*)(Ws + k * D + jc * 16);
#pragma unroll
                for (int q = 0; q < 4; ++q) {
                    float4 wv = wrow[q];
                    acc[q * 4 + 0] = fmaf(xs[kk], wv.x, acc[q * 4 + 0]);
                    acc[q * 4 + 1] = fmaf(xs[kk], wv.y, acc[q * 4 + 1]);
                    acc[q * 4 + 2] = fmaf(xs[kk], wv.z, acc[q * 4 + 2]);
                    acc[q * 4 + 3] = fmaf(xs[kk], wv.w, acc[q * 4 + 3]);
                }
            }
        }
        float4* out4 = (float4*)(H + (size_t)row * D + jc * 16);
#pragma unroll
        for (int q = 0; q < 4; ++q)
            out4[q] = make_float4(acc[q * 4 + 0], acc[q * 4 + 1],
                                  acc[q * 4 + 2], acc[q * 4 + 3]);
    }
}

// ---------------------------------------------------------------------------
// CSR aggregate: 16 lanes per node, register accumulation, fused self-loop
// and ReLU. Payload loads software-pipelined one iteration ahead.
// ---------------------------------------------------------------------------
__global__ void __launch_bounds__(256) k_agg(const float* __restrict__ H,
                                             float* __restrict__ A) {
    int idx = blockIdx.x * 256 + threadIdx.x;
    int n = idx >> 4;
    if (n >= N_NODES) return;
    int l = idx & 15;

    float di = g_dis[n];
    float di2 = di * di;
    float4 hv = ((const float4*)H)[n * 16 + l];
    float4 acc = make_float4(hv.x * di2, hv.y * di2, hv.z * di2, hv.w * di2);

    int e   = g_row[n];
    int end = e + g_cnt[n];

    int2 p = (e < end) ? g_bins[e] : make_int2(0, 0);
    while (e < end) {
        int2 cur = p;
        ++e;
        if (e < end) p = g_bins[e];               // prefetch next payload
        float nm = __int_as_float(cur.y);
        float4 v = ((const float4*)H)[cur.x * 16 + l];
        acc.x = fmaf(nm, v.x, acc.x);
        acc.y = fmaf(nm, v.y, acc.y);
        acc.z = fmaf(nm, v.z, acc.z);
        acc.w = fmaf(nm, v.w, acc.w);
    }

    acc.x = fmaxf(acc.x, 0.f); acc.y = fmaxf(acc.y, 0.f);
    acc.z = fmaxf(acc.z, 0.f); acc.w = fmaxf(acc.w, 0.f);
    ((float4*)A)[n * 16 + l] = acc;
}

// ---------------------------------------------------------------------------
extern "C" void kernel_launch(void* const* d_in, const int* in_sizes, int n_in,
                              void* d_out, int out_size) {
    const float* x   = (const float*)d_in[0];
    const int*   ei  = (const int*)d_in[1];     // int32 (JAX x64 disabled)
    const float* w   = (const float*)d_in[2];
    const float* W0  = (const float*)d_in[3];
    const float* W1  = (const float*)d_in[4];
    float* out = (float*)d_out;

    const int* src = ei;
    const int* dst = ei + N_EDGES;

    float *p_h, *p_agg;
    cudaGetSymbolAddress((void**)&p_h, g_h);
    cudaGetSymbolAddress((void**)&p_agg, g_agg);

    const int TB = 256;
    int gN    = (N_NODES + TB - 1) / TB;
    int gE4   = (N_EDGES / 4 + TB - 1) / TB;
    int gE    = (N_EDGES + TB - 1) / TB;
    int gAgg  = (N_NODES * 16 + TB - 1) / TB;
    int gGemm = (N_NODES + 127) / 128;

    // prep: degrees + CSR
    k_init<<<gN, TB>>>();
    k_hist<<<gE4, TB>>>(dst, w);
    k_rsqrt<<<gN, TB>>>();
    k_reduce<<<NB, SCAN_BS>>>();
    k_scanp<<<1, 256>>>();
    k_offsets<<<NB, SCAN_BS>>>();
    k_fill<<<gE, TB>>>(src, dst, w);

    // layer 1
    k_gemm<<<gGemm, 128>>>(x, W0, p_h);
    k_agg<<<gAgg, TB>>>(p_h, p_agg);

    // layer 2
    k_gemm<<<gGemm, 128>>>(p_agg, W1, p_h);
    k_agg<<<gAgg, TB>>>(p_h, out);
}

// round 5
// speedup vs baseline: 1.4810x; 1.1008x over previous
#include <cuda_runtime.h>
#include <cstdint>

// GCN 2-layer, CSR two-phase aggregation (no feature atomics), sm_100a.
//   prep:  hist(deg,cnt) -> alloc(rsqrt + atomic row offsets) -> fill bins
//   layer: H = X@W ; A[n] = relu(dis^2*H[n] + sum_bin norm*H[src]) (x4 MLP)

#define N_NODES 100000
#define N_EDGES 1600000
#define D 64

__device__ float g_dis[N_NODES];        // rsqrt(degree)
__device__ int   g_cnt[N_NODES];        // in-degree (edges only)
__device__ int   g_row[N_NODES];        // CSR row start (atomic-allocated)
__device__ int   g_cur[N_NODES];        // fill cursor
__device__ int   g_total;               // bump allocator
__device__ int2  g_bins[N_EDGES];       // (src, norm-as-int), dst-binned
__device__ float g_h[N_NODES * D];      // X@W result (both layers)
__device__ float g_agg[N_NODES * D];    // layer-1 output

// ---------------------------------------------------------------------------
__global__ void k_init() {
    int i = blockIdx.x * blockDim.x + threadIdx.x;
    if (i < N_NODES) { g_dis[i] = 1.0f; g_cnt[i] = 0; }
    if (i == 0) g_total = 0;
}

// weighted degree + count histogram, 4 edges/thread
__global__ void k_hist(const int* __restrict__ dst,
                       const float* __restrict__ w) {
    int t = blockIdx.x * blockDim.x + threadIdx.x;
    if (t >= N_EDGES / 4) return;
    int4   dv = ((const int4*)dst)[t];
    float4 wv = ((const float4*)w)[t];
    atomicAdd(&g_dis[dv.x], wv.x);  atomicAdd(&g_cnt[dv.x], 1);
    atomicAdd(&g_dis[dv.y], wv.y);  atomicAdd(&g_cnt[dv.y], 1);
    atomicAdd(&g_dis[dv.z], wv.z);  atomicAdd(&g_cnt[dv.z], 1);
    atomicAdd(&g_dis[dv.w], wv.w);  atomicAdd(&g_cnt[dv.w], 1);
}

// rsqrt + bump-allocate bin ranges (order-irrelevant; no scan needed)
__global__ void k_alloc() {
    int i = blockIdx.x * blockDim.x + threadIdx.x;
    if (i >= N_NODES) return;
    g_dis[i] = rsqrtf(g_dis[i]);
    int r = atomicAdd(&g_total, g_cnt[i]);
    g_row[i] = r;
    g_cur[i] = r;
}

// fill bins: 4 edges/thread; norm computed inline; cursor-atomic placement
__global__ void k_fill(const int* __restrict__ src,
                       const int* __restrict__ dst,
                       const float* __restrict__ w) {
    int t = blockIdx.x * blockDim.x + threadIdx.x;
    if (t >= N_EDGES / 4) return;
    int4   sv = ((const int4*)src)[t];
    int4   dv = ((const int4*)dst)[t];
    float4 wv = ((const float4*)w)[t];
    float ss0 = g_dis[sv.x], ss1 = g_dis[sv.y], ss2 = g_dis[sv.z], ss3 = g_dis[sv.w];
    float dd0 = g_dis[dv.x], dd1 = g_dis[dv.y], dd2 = g_dis[dv.z], dd3 = g_dis[dv.w];
    int p0 = atomicAdd(&g_cur[dv.x], 1);
    int p1 = atomicAdd(&g_cur[dv.y], 1);
    int p2 = atomicAdd(&g_cur[dv.z], 1);
    int p3 = atomicAdd(&g_cur[dv.w], 1);
    g_bins[p0] = make_int2(sv.x, __float_as_int(ss0 * wv.x * dd0));
    g_bins[p1] = make_int2(sv.y, __float_as_int(ss1 * wv.y * dd1));
    g_bins[p2] = make_int2(sv.z, __float_as_int(ss2 * wv.z * dd2));
    g_bins[p3] = make_int2(sv.w, __float_as_int(ss3 * wv.w * dd3));
}

// ---------------------------------------------------------------------------
// dense 64x64 GEMM: H[row] = X[row] @ W ; one thread per node row
// ---------------------------------------------------------------------------
__global__ void __launch_bounds__(128) k_gemm(const float* __restrict__ X,
                                              const float* __restrict__ W,
                                              float* __restrict__ H) {
    __shared__ float Ws[D * D];
    int tid = threadIdx.x;
    {
        const float4* W4 = (const float4*)W;
        float4* Ws4 = (float4*)Ws;
#pragma unroll
        for (int i = 0; i < 8; ++i) Ws4[tid + i * 128] = W4[tid + i * 128];
    }
    __syncthreads();

    int row = blockIdx.x * 128 + tid;
    if (row >= N_NODES) return;

    const float4* x4 = (const float4*)(X + (size_t)row * D);

#pragma unroll 1
    for (int jc = 0; jc < 4; ++jc) {
        float acc[16];
#pragma unroll
        for (int j = 0; j < 16; ++j) acc[j] = 0.f;

#pragma unroll
        for (int k4 = 0; k4 < 16; ++k4) {
            float4 xv = x4[k4];
            float xs[4] = {xv.x, xv.y, xv.z, xv.w};
#pragma unroll
            for (int kk = 0; kk < 4; ++kk) {
                int k = k4 * 4 + kk;
                const float4* wrow = (const float4*)(Ws + k * D + jc * 16);
#pragma unroll
                for (int q = 0; q < 4; ++q) {
                    float4 wv = wrow[q];
                    acc[q * 4 + 0] = fmaf(xs[kk], wv.x, acc[q * 4 + 0]);
                    acc[q * 4 + 1] = fmaf(xs[kk], wv.y, acc[q * 4 + 1]);
                    acc[q * 4 + 2] = fmaf(xs[kk], wv.z, acc[q * 4 + 2]);
                    acc[q * 4 + 3] = fmaf(xs[kk], wv.w, acc[q * 4 + 3]);
                }
            }
        }
        float4* out4 = (float4*)(H + (size_t)row * D + jc * 16);
#pragma unroll
        for (int q = 0; q < 4; ++q)
            out4[q] = make_float4(acc[q * 4 + 0], acc[q * 4 + 1],
                                  acc[q * 4 + 2], acc[q * 4 + 3]);
    }
}

// ---------------------------------------------------------------------------
// CSR aggregate: 16 lanes per node, register accumulation, fused self-loop
// and ReLU. Edge loop unrolled x4: 4 payloads then 4 independent gathers
// in flight per lane (MLP=4).
// ---------------------------------------------------------------------------
__global__ void __launch_bounds__(256) k_agg(const float* __restrict__ H,
                                             float* __restrict__ A) {
    int idx = blockIdx.x * 256 + threadIdx.x;
    int n = idx >> 4;
    if (n >= N_NODES) return;
    int l = idx & 15;

    int e   = g_row[n];
    int end = e + g_cnt[n];

    float di = g_dis[n];
    float di2 = di * di;
    float4 hv = ((const float4*)H)[n * 16 + l];
    float4 acc = make_float4(hv.x * di2, hv.y * di2, hv.z * di2, hv.w * di2);

    // unrolled-by-4 main loop: batch payloads, then batch gathers
    for (; e + 4 <= end; e += 4) {
        int2 p0 = g_bins[e + 0];
        int2 p1 = g_bins[e + 1];
        int2 p2 = g_bins[e + 2];
        int2 p3 = g_bins[e + 3];
        float4 v0 = ((const float4*)H)[p0.x * 16 + l];
        float4 v1 = ((const float4*)H)[p1.x * 16 + l];
        float4 v2 = ((const float4*)H)[p2.x * 16 + l];
        float4 v3 = ((const float4*)H)[p3.x * 16 + l];
        float n0 = __int_as_float(p0.y), n1 = __int_as_float(p1.y);
        float n2 = __int_as_float(p2.y), n3 = __int_as_float(p3.y);
        acc.x = fmaf(n0, v0.x, acc.x); acc.y = fmaf(n0, v0.y, acc.y);
        acc.z = fmaf(n0, v0.z, acc.z); acc.w = fmaf(n0, v0.w, acc.w);
        acc.x = fmaf(n1, v1.x, acc.x); acc.y = fmaf(n1, v1.y, acc.y);
        acc.z = fmaf(n1, v1.z, acc.z); acc.w = fmaf(n1, v1.w, acc.w);
        acc.x = fmaf(n2, v2.x, acc.x); acc.y = fmaf(n2, v2.y, acc.y);
        acc.z = fmaf(n2, v2.z, acc.z); acc.w = fmaf(n2, v2.w, acc.w);
        acc.x = fmaf(n3, v3.x, acc.x); acc.y = fmaf(n3, v3.y, acc.y);
        acc.z = fmaf(n3, v3.z, acc.z); acc.w = fmaf(n3, v3.w, acc.w);
    }
    // remainder
    for (; e < end; ++e) {
        int2 p = g_bins[e];
        float nm = __int_as_float(p.y);
        float4 v = ((const float4*)H)[p.x * 16 + l];
        acc.x = fmaf(nm, v.x, acc.x); acc.y = fmaf(nm, v.y, acc.y);
        acc.z = fmaf(nm, v.z, acc.z); acc.w = fmaf(nm, v.w, acc.w);
    }

    acc.x = fmaxf(acc.x, 0.f); acc.y = fmaxf(acc.y, 0.f);
    acc.z = fmaxf(acc.z, 0.f); acc.w = fmaxf(acc.w, 0.f);
    ((float4*)A)[n * 16 + l] = acc;
}

// ---------------------------------------------------------------------------
extern "C" void kernel_launch(void* const* d_in, const int* in_sizes, int n_in,
                              void* d_out, int out_size) {
    const float* x   = (const float*)d_in[0];
    const int*   ei  = (const int*)d_in[1];     // int32 (JAX x64 disabled)
    const float* w   = (const float*)d_in[2];
    const float* W0  = (const float*)d_in[3];
    const float* W1  = (const float*)d_in[4];
    float* out = (float*)d_out;

    const int* src = ei;
    const int* dst = ei + N_EDGES;

    float *p_h, *p_agg;
    cudaGetSymbolAddress((void**)&p_h, g_h);
    cudaGetSymbolAddress((void**)&p_agg, g_agg);

    const int TB = 256;
    int gN    = (N_NODES + TB - 1) / TB;
    int gE4   = (N_EDGES / 4 + TB - 1) / TB;
    int gAgg  = (N_NODES * 16 + TB - 1) / TB;
    int gGemm = (N_NODES + 127) / 128;

    // prep: degrees + CSR (bump-allocated bins; order-irrelevant)
    k_init<<<gN, TB>>>();
    k_hist<<<gE4, TB>>>(dst, w);
    k_alloc<<<gN, TB>>>();
    k_fill<<<gE4, TB>>>(src, dst, w);

    // layer 1
    k_gemm<<<gGemm, 128>>>(x, W0, p_h);
    k_agg<<<gAgg, TB>>>(p_h, p_agg);

    // layer 2
    k_gemm<<<gGemm, 128>>>(p_agg, W1, p_h);
    k_agg<<<gAgg, TB>>>(p_h, out);
}

// round 6
// speedup vs baseline: 1.5095x; 1.0192x over previous
#include <cuda_runtime.h>
#include <cstdint>

// GCN 2-layer, CSR two-phase aggregation (no feature atomics), sm_100a.
//   prep:  hist(deg, cnt->pos) -> alloc(rsqrt + bump row offsets) -> fill bins
//   layer: H = X@W ; A[n] = relu(dis^2*H[n] + sum_bin norm*H[src]) (x8 MLP)

#define N_NODES 100000
#define N_EDGES 1600000
#define D 64

__device__ float g_dis[N_NODES];        // rsqrt(degree)
__device__ int   g_cnt[N_NODES];        // in-degree (edges only)
__device__ int   g_row[N_NODES];        // CSR row start (bump-allocated)
__device__ int   g_total;               // bump allocator
__device__ int   g_pos[N_EDGES];        // within-bin slot (from hist atomic)
__device__ int2  g_bins[N_EDGES];       // (src, norm-as-int), dst-binned
__device__ float g_h[N_NODES * D];      // X@W result (both layers)
__device__ float g_agg[N_NODES * D];    // layer-1 output

// ---------------------------------------------------------------------------
__global__ void k_init() {
    int i = blockIdx.x * blockDim.x + threadIdx.x;
    if (i < N_NODES) { g_dis[i] = 1.0f; g_cnt[i] = 0; }
    if (i == 0) g_total = 0;
}

// weighted degree + count histogram; the cnt atomic's return IS the
// within-bin position -> saved to g_pos (coalesced int4).
__global__ void k_hist(const int* __restrict__ dst,
                       const float* __restrict__ w) {
    int t = blockIdx.x * blockDim.x + threadIdx.x;
    if (t >= N_EDGES / 4) return;
    int4   dv = ((const int4*)dst)[t];
    float4 wv = ((const float4*)w)[t];
    atomicAdd(&g_dis[dv.x], wv.x);
    atomicAdd(&g_dis[dv.y], wv.y);
    atomicAdd(&g_dis[dv.z], wv.z);
    atomicAdd(&g_dis[dv.w], wv.w);
    int p0 = atomicAdd(&g_cnt[dv.x], 1);
    int p1 = atomicAdd(&g_cnt[dv.y], 1);
    int p2 = atomicAdd(&g_cnt[dv.z], 1);
    int p3 = atomicAdd(&g_cnt[dv.w], 1);
    ((int4*)g_pos)[t] = make_int4(p0, p1, p2, p3);
}

// rsqrt + bump-allocate bin ranges (order-irrelevant; no scan needed)
__global__ void k_alloc() {
    int i = blockIdx.x * blockDim.x + threadIdx.x;
    if (i >= N_NODES) return;
    g_dis[i] = rsqrtf(g_dis[i]);
    g_row[i] = atomicAdd(&g_total, g_cnt[i]);
}

// fill bins: atomic-free; slot = row[dst] + pos[e]; norm computed inline
__global__ void k_fill(const int* __restrict__ src,
                       const int* __restrict__ dst,
                       const float* __restrict__ w) {
    int t = blockIdx.x * blockDim.x + threadIdx.x;
    if (t >= N_EDGES / 4) return;
    int4   sv = ((const int4*)src)[t];
    int4   dv = ((const int4*)dst)[t];
    int4   pv = ((const int4*)g_pos)[t];
    float4 wv = ((const float4*)w)[t];
    float ss0 = g_dis[sv.x], ss1 = g_dis[sv.y], ss2 = g_dis[sv.z], ss3 = g_dis[sv.w];
    float dd0 = g_dis[dv.x], dd1 = g_dis[dv.y], dd2 = g_dis[dv.z], dd3 = g_dis[dv.w];
    int r0 = g_row[dv.x], r1 = g_row[dv.y], r2 = g_row[dv.z], r3 = g_row[dv.w];
    g_bins[r0 + pv.x] = make_int2(sv.x, __float_as_int(ss0 * wv.x * dd0));
    g_bins[r1 + pv.y] = make_int2(sv.y, __float_as_int(ss1 * wv.y * dd1));
    g_bins[r2 + pv.z] = make_int2(sv.z, __float_as_int(ss2 * wv.z * dd2));
    g_bins[r3 + pv.w] = make_int2(sv.w, __float_as_int(ss3 * wv.w * dd3));
}

// ---------------------------------------------------------------------------
// dense 64x64 GEMM: H[row] = X[row] @ W ; one thread per node row
// ---------------------------------------------------------------------------
__global__ void __launch_bounds__(128) k_gemm(const float* __restrict__ X,
                                              const float* __restrict__ W,
                                              float* __restrict__ H) {
    __shared__ float Ws[D * D];
    int tid = threadIdx.x;
    {
        const float4* W4 = (const float4*)W;
        float4* Ws4 = (float4*)Ws;
#pragma unroll
        for (int i = 0; i < 8; ++i) Ws4[tid + i * 128] = W4[tid + i * 128];
    }
    __syncthreads();

    int row = blockIdx.x * 128 + tid;
    if (row >= N_NODES) return;

    const float4* x4 = (const float4*)(X + (size_t)row * D);

#pragma unroll 1
    for (int jc = 0; jc < 4; ++jc) {
        float acc[16];
#pragma unroll
        for (int j = 0; j < 16; ++j) acc[j] = 0.f;

#pragma unroll
        for (int k4 = 0; k4 < 16; ++k4) {
            float4 xv = x4[k4];
            float xs[4] = {xv.x, xv.y, xv.z, xv.w};
#pragma unroll
            for (int kk = 0; kk < 4; ++kk) {
                int k = k4 * 4 + kk;
                const float4* wrow = (const float4*)(Ws + k * D + jc * 16);
#pragma unroll
                for (int q = 0; q < 4; ++q) {
                    float4 wv = wrow[q];
                    acc[q * 4 + 0] = fmaf(xs[kk], wv.x, acc[q * 4 + 0]);
                    acc[q * 4 + 1] = fmaf(xs[kk], wv.y, acc[q * 4 + 1]);
                    acc[q * 4 + 2] = fmaf(xs[kk], wv.z, acc[q * 4 + 2]);
                    acc[q * 4 + 3] = fmaf(xs[kk], wv.w, acc[q * 4 + 3]);
                }
            }
        }
        float4* out4 = (float4*)(H + (size_t)row * D + jc * 16);
#pragma unroll
        for (int q = 0; q < 4; ++q)
            out4[q] = make_float4(acc[q * 4 + 0], acc[q * 4 + 1],
                                  acc[q * 4 + 2], acc[q * 4 + 3]);
    }
}

// ---------------------------------------------------------------------------
// CSR aggregate: 16 lanes per node, register accumulation, fused self-loop
// and ReLU. Edge loop unrolled x8 (8 payloads then 8 independent gathers).
// ---------------------------------------------------------------------------
__global__ void __launch_bounds__(256) k_agg(const float* __restrict__ H,
                                             float* __restrict__ A) {
    int idx = blockIdx.x * 256 + threadIdx.x;
    int n = idx >> 4;
    if (n >= N_NODES) return;
    int l = idx & 15;

    int e   = g_row[n];
    int end = e + g_cnt[n];

    float di = g_dis[n];
    float di2 = di * di;
    float4 hv = ((const float4*)H)[n * 16 + l];
    float4 acc = make_float4(hv.x * di2, hv.y * di2, hv.z * di2, hv.w * di2);

    // x8: batch payload loads, then batch gathers (MLP=8)
    for (; e + 8 <= end; e += 8) {
        int2 p[8];
#pragma unroll
        for (int j = 0; j < 8; ++j) p[j] = g_bins[e + j];
        float4 v[8];
#pragma unroll
        for (int j = 0; j < 8; ++j) v[j] = ((const float4*)H)[p[j].x * 16 + l];
#pragma unroll
        for (int j = 0; j < 8; ++j) {
            float nm = __int_as_float(p[j].y);
            acc.x = fmaf(nm, v[j].x, acc.x);
            acc.y = fmaf(nm, v[j].y, acc.y);
            acc.z = fmaf(nm, v[j].z, acc.z);
            acc.w = fmaf(nm, v[j].w, acc.w);
        }
    }
    // x4 mid
    if (e + 4 <= end) {
        int2 p[4];
#pragma unroll
        for (int j = 0; j < 4; ++j) p[j] = g_bins[e + j];
        float4 v[4];
#pragma unroll
        for (int j = 0; j < 4; ++j) v[j] = ((const float4*)H)[p[j].x * 16 + l];
#pragma unroll
        for (int j = 0; j < 4; ++j) {
            float nm = __int_as_float(p[j].y);
            acc.x = fmaf(nm, v[j].x, acc.x);
            acc.y = fmaf(nm, v[j].y, acc.y);
            acc.z = fmaf(nm, v[j].z, acc.z);
            acc.w = fmaf(nm, v[j].w, acc.w);
        }
        e += 4;
    }
    // scalar remainder
    for (; e < end; ++e) {
        int2 p = g_bins[e];
        float nm = __int_as_float(p.y);
        float4 v = ((const float4*)H)[p.x * 16 + l];
        acc.x = fmaf(nm, v.x, acc.x); acc.y = fmaf(nm, v.y, acc.y);
        acc.z = fmaf(nm, v.z, acc.z); acc.w = fmaf(nm, v.w, acc.w);
    }

    acc.x = fmaxf(acc.x, 0.f); acc.y = fmaxf(acc.y, 0.f);
    acc.z = fmaxf(acc.z, 0.f); acc.w = fmaxf(acc.w, 0.f);
    ((float4*)A)[n * 16 + l] = acc;
}

// ---------------------------------------------------------------------------
extern "C" void kernel_launch(void* const* d_in, const int* in_sizes, int n_in,
                              void* d_out, int out_size) {
    const float* x   = (const float*)d_in[0];
    const int*   ei  = (const int*)d_in[1];     // int32 (JAX x64 disabled)
    const float* w   = (const float*)d_in[2];
    const float* W0  = (const float*)d_in[3];
    const float* W1  = (const float*)d_in[4];
    float* out = (float*)d_out;

    const int* src = ei;
    const int* dst = ei + N_EDGES;

    float *p_h, *p_agg;
    cudaGetSymbolAddress((void**)&p_h, g_h);
    cudaGetSymbolAddress((void**)&p_agg, g_agg);

    const int TB = 256;
    int gN    = (N_NODES + TB - 1) / TB;
    int gE4   = (N_EDGES / 4 + TB - 1) / TB;
    int gAgg  = (N_NODES * 16 + TB - 1) / TB;
    int gGemm = (N_NODES + 127) / 128;

    // prep: degrees + CSR (atomic-free fill via hist-returned positions)
    k_init<<<gN, TB>>>();
    k_hist<<<gE4, TB>>>(dst, w);
    k_alloc<<<gN, TB>>>();
    k_fill<<<gE4, TB>>>(src, dst, w);

    // layer 1
    k_gemm<<<gGemm, 128>>>(x, W0, p_h);
    k_agg<<<gAgg, TB>>>(p_h, p_agg);

    // layer 2
    k_gemm<<<gGemm, 128>>>(p_agg, W1, p_h);
    k_agg<<<gAgg, TB>>>(p_h, out);
}

// round 7
// speedup vs baseline: 1.6700x; 1.1064x over previous
#include <cuda_runtime.h>
#include <cstdint>

// GCN 2-layer, CSR two-phase aggregation, sm_100a.
// Factored normalization: Hs = dis*(X@W); agg = relu(dis*(Hs[n] + sum w*Hs[src]))
//   prep:  packed hist(cnt|fixsum, pos) -> alloc -> fill bins(src,w) [1 gather]
//   layer: Hs = dis*(X@W) ; A[n] = relu(dis[n]*(Hs[n] + sum_bin w*Hs[src]))

#define N_NODES 100000
#define N_EDGES 1600000
#define D 64
#define FIXS 33554432.0f          // 2^25 fixed-point scale for weight sums
#define FIXR (1.0f / 33554432.0f)

__device__ unsigned long long g_pk[N_NODES];  // (cnt << 32) | fixed_weight_sum
__device__ float g_dis[N_NODES];        // rsqrt(degree)
__device__ int   g_cnt[N_NODES];        // in-degree (edges only)
__device__ int   g_row[N_NODES];        // CSR row start (bump-allocated)
__device__ int   g_total;               // bump allocator
__device__ int   g_pos[N_EDGES];        // within-bin slot (from hist atomic)
__device__ int2  g_bins[N_EDGES];       // (src, w-as-int), dst-binned
__device__ float g_h[N_NODES * D];      // Hs = dis*(X@W)
__device__ float g_agg[N_NODES * D];    // layer-1 output

// ---------------------------------------------------------------------------
__global__ void k_init() {
    int i = blockIdx.x * blockDim.x + threadIdx.x;
    if (i < N_NODES) g_pk[i] = 0ULL;
    if (i == 0) g_total = 0;
}

// one packed 64-bit atomic per edge: count (hi) + fixed-point weight sum (lo).
// return's hi 32 bits = within-bin position.
__global__ void k_hist(const int* __restrict__ dst,
                       const float* __restrict__ w) {
    int t = blockIdx.x * blockDim.x + threadIdx.x;
    if (t >= N_EDGES / 4) return;
    int4   dv = ((const int4*)dst)[t];
    float4 wv = ((const float4*)w)[t];
    unsigned long long a0 = (1ULL << 32) | (unsigned)__float2uint_rn(wv.x * FIXS);
    unsigned long long a1 = (1ULL << 32) | (unsigned)__float2uint_rn(wv.y * FIXS);
    unsigned long long a2 = (1ULL << 32) | (unsigned)__float2uint_rn(wv.z * FIXS);
    unsigned long long a3 = (1ULL << 32) | (unsigned)__float2uint_rn(wv.w * FIXS);
    int p0 = (int)(atomicAdd(&g_pk[dv.x], a0) >> 32);
    int p1 = (int)(atomicAdd(&g_pk[dv.y], a1) >> 32);
    int p2 = (int)(atomicAdd(&g_pk[dv.z], a2) >> 32);
    int p3 = (int)(atomicAdd(&g_pk[dv.w], a3) >> 32);
    ((int4*)g_pos)[t] = make_int4(p0, p1, p2, p3);
}

// unpack, rsqrt, bump-allocate bin ranges
__global__ void k_alloc() {
    int i = blockIdx.x * blockDim.x + threadIdx.x;
    if (i >= N_NODES) return;
    unsigned long long pk = g_pk[i];
    int cnt = (int)(pk >> 32);
    float deg = 1.0f + (float)(unsigned)(pk & 0xFFFFFFFFULL) * FIXR;
    g_dis[i] = rsqrtf(deg);
    g_cnt[i] = cnt;
    g_row[i] = atomicAdd(&g_total, cnt);
}

// fill bins: payload is (src, raw w) — no dis gathers; one row[dst] gather
__global__ void k_fill(const int* __restrict__ src,
                       const int* __restrict__ dst,
                       const float* __restrict__ w) {
    int t = blockIdx.x * blockDim.x + threadIdx.x;
    if (t >= N_EDGES / 4) return;
    int4   sv = ((const int4*)src)[t];
    int4   dv = ((const int4*)dst)[t];
    int4   pv = ((const int4*)g_pos)[t];
    float4 wv = ((const float4*)w)[t];
    int r0 = g_row[dv.x], r1 = g_row[dv.y], r2 = g_row[dv.z], r3 = g_row[dv.w];
    g_bins[r0 + pv.x] = make_int2(sv.x, __float_as_int(wv.x));
    g_bins[r1 + pv.y] = make_int2(sv.y, __float_as_int(wv.y));
    g_bins[r2 + pv.z] = make_int2(sv.z, __float_as_int(wv.z));
    g_bins[r3 + pv.w] = make_int2(sv.w, __float_as_int(wv.w));
}

// ---------------------------------------------------------------------------
// dense 64x64 GEMM with scaled output: Hs[row] = dis[row] * (X[row] @ W)
// ---------------------------------------------------------------------------
__global__ void __launch_bounds__(128) k_gemm(const float* __restrict__ X,
                                              const float* __restrict__ W,
                                              float* __restrict__ H) {
    __shared__ float Ws[D * D];
    int tid = threadIdx.x;
    {
        const float4* W4 = (const float4*)W;
        float4* Ws4 = (float4*)Ws;
#pragma unroll
        for (int i = 0; i < 8; ++i) Ws4[tid + i * 128] = W4[tid + i * 128];
    }
    __syncthreads();

    int row = blockIdx.x * 128 + tid;
    if (row >= N_NODES) return;

    float di = g_dis[row];
    const float4* x4 = (const float4*)(X + (size_t)row * D);

#pragma unroll 1
    for (int jc = 0; jc < 4; ++jc) {
        float acc[16];
#pragma unroll
        for (int j = 0; j < 16; ++j) acc[j] = 0.f;

#pragma unroll
        for (int k4 = 0; k4 < 16; ++k4) {
            float4 xv = x4[k4];
            float xs[4] = {xv.x, xv.y, xv.z, xv.w};
#pragma unroll
            for (int kk = 0; kk < 4; ++kk) {
                int k = k4 * 4 + kk;
                const float4* wrow = (const float4*)(Ws + k * D + jc * 16);
#pragma unroll
                for (int q = 0; q < 4; ++q) {
                    float4 wv = wrow[q];
                    acc[q * 4 + 0] = fmaf(xs[kk], wv.x, acc[q * 4 + 0]);
                    acc[q * 4 + 1] = fmaf(xs[kk], wv.y, acc[q * 4 + 1]);
                    acc[q * 4 + 2] = fmaf(xs[kk], wv.z, acc[q * 4 + 2]);
                    acc[q * 4 + 3] = fmaf(xs[kk], wv.w, acc[q * 4 + 3]);
                }
            }
        }
        float4* out4 = (float4*)(H + (size_t)row * D + jc * 16);
#pragma unroll
        for (int q = 0; q < 4; ++q)
            out4[q] = make_float4(acc[q * 4 + 0] * di, acc[q * 4 + 1] * di,
                                  acc[q * 4 + 2] * di, acc[q * 4 + 3] * di);
    }
}

// ---------------------------------------------------------------------------
// CSR aggregate: A[n] = relu( dis[n] * (Hs[n] + sum_bin w * Hs[src]) )
// 16 lanes per node; edge loop unrolled x8 (MLP=8).
// ---------------------------------------------------------------------------
__global__ void __launch_bounds__(256) k_agg(const float* __restrict__ H,
                                             float* __restrict__ A) {
    int idx = blockIdx.x * 256 + threadIdx.x;
    int n = idx >> 4;
    if (n >= N_NODES) return;
    int l = idx & 15;

    int e   = g_row[n];
    int end = e + g_cnt[n];

    float4 acc = ((const float4*)H)[n * 16 + l];   // Hs[n] self-loop term

    for (; e + 8 <= end; e += 8) {
        int2 p[8];
#pragma unroll
        for (int j = 0; j < 8; ++j) p[j] = g_bins[e + j];
        float4 v[8];
#pragma unroll
        for (int j = 0; j < 8; ++j) v[j] = ((const float4*)H)[p[j].x * 16 + l];
#pragma unroll
        for (int j = 0; j < 8; ++j) {
            float nm = __int_as_float(p[j].y);
            acc.x = fmaf(nm, v[j].x, acc.x);
            acc.y = fmaf(nm, v[j].y, acc.y);
            acc.z = fmaf(nm, v[j].z, acc.z);
            acc.w = fmaf(nm, v[j].w, acc.w);
        }
    }
    if (e + 4 <= end) {
        int2 p[4];
#pragma unroll
        for (int j = 0; j < 4; ++j) p[j] = g_bins[e + j];
        float4 v[4];
#pragma unroll
        for (int j = 0; j < 4; ++j) v[j] = ((const float4*)H)[p[j].x * 16 + l];
#pragma unroll
        for (int j = 0; j < 4; ++j) {
            float nm = __int_as_float(p[j].y);
            acc.x = fmaf(nm, v[j].x, acc.x);
            acc.y = fmaf(nm, v[j].y, acc.y);
            acc.z = fmaf(nm, v[j].z, acc.z);
            acc.w = fmaf(nm, v[j].w, acc.w);
        }
        e += 4;
    }
    for (; e < end; ++e) {
        int2 p = g_bins[e];
        float nm = __int_as_float(p.y);
        float4 v = ((const float4*)H)[p.x * 16 + l];
        acc.x = fmaf(nm, v.x, acc.x); acc.y = fmaf(nm, v.y, acc.y);
        acc.z = fmaf(nm, v.z, acc.z); acc.w = fmaf(nm, v.w, acc.w);
    }

    float di = g_dis[n];
    acc.x = fmaxf(acc.x * di, 0.f); acc.y = fmaxf(acc.y * di, 0.f);
    acc.z = fmaxf(acc.z * di, 0.f); acc.w = fmaxf(acc.w * di, 0.f);
    ((float4*)A)[n * 16 + l] = acc;
}

// ---------------------------------------------------------------------------
extern "C" void kernel_launch(void* const* d_in, const int* in_sizes, int n_in,
                              void* d_out, int out_size) {
    const float* x   = (const float*)d_in[0];
    const int*   ei  = (const int*)d_in[1];     // int32 (JAX x64 disabled)
    const float* w   = (const float*)d_in[2];
    const float* W0  = (const float*)d_in[3];
    const float* W1  = (const float*)d_in[4];
    float* out = (float*)d_out;

    const int* src = ei;
    const int* dst = ei + N_EDGES;

    float *p_h, *p_agg;
    cudaGetSymbolAddress((void**)&p_h, g_h);
    cudaGetSymbolAddress((void**)&p_agg, g_agg);

    const int TB = 256;
    int gN    = (N_NODES + TB - 1) / TB;
    int gE4   = (N_EDGES / 4 + TB - 1) / TB;
    int gAgg  = (N_NODES * 16 + TB - 1) / TB;
    int gGemm = (N_NODES + 127) / 128;

    // prep
    k_init<<<gN, TB>>>();
    k_hist<<<gE4, TB>>>(dst, w);
    k_alloc<<<gN, TB>>>();
    k_fill<<<gE4, TB>>>(src, dst, w);

    // layer 1
    k_gemm<<<gGemm, 128>>>(x, W0, p_h);
    k_agg<<<gAgg, TB>>>(p_h, p_agg);

    // layer 2
    k_gemm<<<gGemm, 128>>>(p_agg, W1, p_h);
    k_agg<<<gAgg, TB>>>(p_h, out);
}

// round 8
// speedup vs baseline: 1.7064x; 1.0217x over previous
#include <cuda_runtime.h>
#include <cuda_fp16.h>
#include <cstdint>

// GCN 2-layer, CSR two-phase aggregation, sm_100a.
// Hs = dis*(X@W) stored fp16 (halves gather traffic); fp32 accumulation.
//   prep:  packed hist(cnt|fixsum, pos) -> alloc -> fill bins(src,w)
//   layer: Hs(half) = dis*(X@W) ; A[n] = relu(dis[n]*(Hs[n] + sum w*Hs[src]))

#define N_NODES 100000
#define N_EDGES 1600000
#define D 64
#define FIXS 33554432.0f          // 2^25 fixed-point scale for weight sums
#define FIXR (1.0f / 33554432.0f)

__device__ unsigned long long g_pk[N_NODES];  // (cnt << 32) | fixed_weight_sum
__device__ float g_dis[N_NODES];        // rsqrt(degree)
__device__ int   g_cnt[N_NODES];        // in-degree (edges only)
__device__ int   g_row[N_NODES];        // CSR row start (bump-allocated)
__device__ int   g_total;               // bump allocator
__device__ int   g_pos[N_EDGES];        // within-bin slot (from hist atomic)
__device__ int2  g_bins[N_EDGES];       // (src, w-as-int), dst-binned
__device__ uint4 g_h[N_NODES * 8];      // Hs as fp16: 64 half = 8 uint4 per node
__device__ float g_agg[N_NODES * D];    // layer-1 output (fp32)

// ---------------------------------------------------------------------------
__global__ void k_init() {
    int i = blockIdx.x * blockDim.x + threadIdx.x;
    if (i < N_NODES) g_pk[i] = 0ULL;
    if (i == 0) g_total = 0;
}

// one packed 64-bit atomic per edge: count (hi) + fixed-point weight sum (lo).
__global__ void k_hist(const int* __restrict__ dst,
                       const float* __restrict__ w) {
    int t = blockIdx.x * blockDim.x + threadIdx.x;
    if (t >= N_EDGES / 4) return;
    int4   dv = ((const int4*)dst)[t];
    float4 wv = ((const float4*)w)[t];
    unsigned long long a0 = (1ULL << 32) | (unsigned)__float2uint_rn(wv.x * FIXS);
    unsigned long long a1 = (1ULL << 32) | (unsigned)__float2uint_rn(wv.y * FIXS);
    unsigned long long a2 = (1ULL << 32) | (unsigned)__float2uint_rn(wv.z * FIXS);
    unsigned long long a3 = (1ULL << 32) | (unsigned)__float2uint_rn(wv.w * FIXS);
    int p0 = (int)(atomicAdd(&g_pk[dv.x], a0) >> 32);
    int p1 = (int)(atomicAdd(&g_pk[dv.y], a1) >> 32);
    int p2 = (int)(atomicAdd(&g_pk[dv.z], a2) >> 32);
    int p3 = (int)(atomicAdd(&g_pk[dv.w], a3) >> 32);
    ((int4*)g_pos)[t] = make_int4(p0, p1, p2, p3);
}

__global__ void k_alloc() {
    int i = blockIdx.x * blockDim.x + threadIdx.x;
    if (i >= N_NODES) return;
    unsigned long long pk = g_pk[i];
    int cnt = (int)(pk >> 32);
    float deg = 1.0f + (float)(unsigned)(pk & 0xFFFFFFFFULL) * FIXR;
    g_dis[i] = rsqrtf(deg);
    g_cnt[i] = cnt;
    g_row[i] = atomicAdd(&g_total, cnt);
}

// fill bins: payload (src, raw w); one row[dst] gather, no dis gathers
__global__ void k_fill(const int* __restrict__ src,
                       const int* __restrict__ dst,
                       const float* __restrict__ w) {
    int t = blockIdx.x * blockDim.x + threadIdx.x;
    if (t >= N_EDGES / 4) return;
    int4   sv = ((const int4*)src)[t];
    int4   dv = ((const int4*)dst)[t];
    int4   pv = ((const int4*)g_pos)[t];
    float4 wv = ((const float4*)w)[t];
    int r0 = g_row[dv.x], r1 = g_row[dv.y], r2 = g_row[dv.z], r3 = g_row[dv.w];
    g_bins[r0 + pv.x] = make_int2(sv.x, __float_as_int(wv.x));
    g_bins[r1 + pv.y] = make_int2(sv.y, __float_as_int(wv.y));
    g_bins[r2 + pv.z] = make_int2(sv.z, __float_as_int(wv.z));
    g_bins[r3 + pv.w] = make_int2(sv.w, __float_as_int(wv.w));
}

// ---------------------------------------------------------------------------
// dense 64x64 GEMM, fp16 output: Hs[row] = half( dis[row] * (X[row] @ W) )
// ---------------------------------------------------------------------------
__global__ void __launch_bounds__(128) k_gemm(const float* __restrict__ X,
                                              const float* __restrict__ W,
                                              uint4* __restrict__ H) {
    __shared__ float Ws[D * D];
    int tid = threadIdx.x;
    {
        const float4* W4 = (const float4*)W;
        float4* Ws4 = (float4*)Ws;
#pragma unroll
        for (int i = 0; i < 8; ++i) Ws4[tid + i * 128] = W4[tid + i * 128];
    }
    __syncthreads();

    int row = blockIdx.x * 128 + tid;
    if (row >= N_NODES) return;

    float di = g_dis[row];
    const float4* x4 = (const float4*)(X + (size_t)row * D);

#pragma unroll 1
    for (int jc = 0; jc < 4; ++jc) {            // 16 output channels per chunk
        float acc[16];
#pragma unroll
        for (int j = 0; j < 16; ++j) acc[j] = 0.f;

#pragma unroll
        for (int k4 = 0; k4 < 16; ++k4) {
            float4 xv = x4[k4];
            float xs[4] = {xv.x, xv.y, xv.z, xv.w};
#pragma unroll
            for (int kk = 0; kk < 4; ++kk) {
                int k = k4 * 4 + kk;
                const float4* wrow = (const float4*)(Ws + k * D + jc * 16);
#pragma unroll
                for (int q = 0; q < 4; ++q) {
                    float4 wv = wrow[q];
                    acc[q * 4 + 0] = fmaf(xs[kk], wv.x, acc[q * 4 + 0]);
                    acc[q * 4 + 1] = fmaf(xs[kk], wv.y, acc[q * 4 + 1]);
                    acc[q * 4 + 2] = fmaf(xs[kk], wv.z, acc[q * 4 + 2]);
                    acc[q * 4 + 3] = fmaf(xs[kk], wv.w, acc[q * 4 + 3]);
                }
            }
        }
        // pack 16 fp32 -> 8 half2 -> 2 uint4
        unsigned pk[8];
#pragma unroll
        for (int q = 0; q < 8; ++q) {
            __half2 h2 = __floats2half2_rn(acc[q * 2] * di, acc[q * 2 + 1] * di);
            pk[q] = *(unsigned*)&h2;
        }
        H[(size_t)row * 8 + jc * 2 + 0] = make_uint4(pk[0], pk[1], pk[2], pk[3]);
        H[(size_t)row * 8 + jc * 2 + 1] = make_uint4(pk[4], pk[5], pk[6], pk[7]);
    }
}

// ---------------------------------------------------------------------------
// CSR aggregate: 8 lanes per node (lane owns 8 channels = 1 uint4 of half2).
// fp32 accumulation; fused self-loop, dis scale, ReLU. x8 unroll (MLP=8).
// ---------------------------------------------------------------------------
__device__ __forceinline__ void acc_half8(float* acc, uint4 v, float nm) {
    float2 f0 = __half22float2(*(__half2*)&v.x);
    float2 f1 = __half22float2(*(__half2*)&v.y);
    float2 f2 = __half22float2(*(__half2*)&v.z);
    float2 f3 = __half22float2(*(__half2*)&v.w);
    acc[0] = fmaf(nm, f0.x, acc[0]); acc[1] = fmaf(nm, f0.y, acc[1]);
    acc[2] = fmaf(nm, f1.x, acc[2]); acc[3] = fmaf(nm, f1.y, acc[3]);
    acc[4] = fmaf(nm, f2.x, acc[4]); acc[5] = fmaf(nm, f2.y, acc[5]);
    acc[6] = fmaf(nm, f3.x, acc[6]); acc[7] = fmaf(nm, f3.y, acc[7]);
}

__global__ void __launch_bounds__(256) k_agg(const uint4* __restrict__ H,
                                             float* __restrict__ A) {
    int idx = blockIdx.x * 256 + threadIdx.x;
    int n = idx >> 3;
    if (n >= N_NODES) return;
    int l = idx & 7;

    int e   = g_row[n];
    int end = e + g_cnt[n];

    float acc[8];
    acc_half8_init:;
    {   // self-loop term Hs[n]
        uint4 sv = H[(size_t)n * 8 + l];
        float2 f0 = __half22float2(*(__half2*)&sv.x);
        float2 f1 = __half22float2(*(__half2*)&sv.y);
        float2 f2 = __half22float2(*(__half2*)&sv.z);
        float2 f3 = __half22float2(*(__half2*)&sv.w);
        acc[0] = f0.x; acc[1] = f0.y; acc[2] = f1.x; acc[3] = f1.y;
        acc[4] = f2.x; acc[5] = f2.y; acc[6] = f3.x; acc[7] = f3.y;
    }

    for (; e + 8 <= end; e += 8) {
        int2 p[8];
#pragma unroll
        for (int j = 0; j < 8; ++j) p[j] = g_bins[e + j];
        uint4 v[8];
#pragma unroll
        for (int j = 0; j < 8; ++j) v[j] = H[(size_t)p[j].x * 8 + l];
#pragma unroll
        for (int j = 0; j < 8; ++j) acc_half8(acc, v[j], __int_as_float(p[j].y));
    }
    if (e + 4 <= end) {
        int2 p[4];
#pragma unroll
        for (int j = 0; j < 4; ++j) p[j] = g_bins[e + j];
        uint4 v[4];
#pragma unroll
        for (int j = 0; j < 4; ++j) v[j] = H[(size_t)p[j].x * 8 + l];
#pragma unroll
        for (int j = 0; j < 4; ++j) acc_half8(acc, v[j], __int_as_float(p[j].y));
        e += 4;
    }
    for (; e < end; ++e) {
        int2 p = g_bins[e];
        uint4 v = H[(size_t)p.x * 8 + l];
        acc_half8(acc, v, __int_as_float(p.y));
    }

    float di = g_dis[n];
    float4 o0 = make_float4(fmaxf(acc[0] * di, 0.f), fmaxf(acc[1] * di, 0.f),
                            fmaxf(acc[2] * di, 0.f), fmaxf(acc[3] * di, 0.f));
    float4 o1 = make_float4(fmaxf(acc[4] * di, 0.f), fmaxf(acc[5] * di, 0.f),
                            fmaxf(acc[6] * di, 0.f), fmaxf(acc[7] * di, 0.f));
    ((float4*)A)[(size_t)n * 16 + l * 2 + 0] = o0;
    ((float4*)A)[(size_t)n * 16 + l * 2 + 1] = o1;
}

// ---------------------------------------------------------------------------
extern "C" void kernel_launch(void* const* d_in, const int* in_sizes, int n_in,
                              void* d_out, int out_size) {
    const float* x   = (const float*)d_in[0];
    const int*   ei  = (const int*)d_in[1];     // int32 (JAX x64 disabled)
    const float* w   = (const float*)d_in[2];
    const float* W0  = (const float*)d_in[3];
    const float* W1  = (const float*)d_in[4];
    float* out = (float*)d_out;

    const int* src = ei;
    const int* dst = ei + N_EDGES;

    uint4* p_h;
    float* p_agg;
    cudaGetSymbolAddress((void**)&p_h, g_h);
    cudaGetSymbolAddress((void**)&p_agg, g_agg);

    const int TB = 256;
    int gN    = (N_NODES + TB - 1) / TB;
    int gE4   = (N_EDGES / 4 + TB - 1) / TB;
    int gAgg  = (N_NODES * 8 + TB - 1) / TB;
    int gGemm = (N_NODES + 127) / 128;

    // prep
    k_init<<<gN, TB>>>();
    k_hist<<<gE4, TB>>>(dst, w);
    k_alloc<<<gN, TB>>>();
    k_fill<<<gE4, TB>>>(src, dst, w);

    // layer 1
    k_gemm<<<gGemm, 128>>>(x, W0, p_h);
    k_agg<<<gAgg, TB>>>(p_h, p_agg);

    // layer 2
    k_gemm<<<gGemm, 128>>>(p_agg, W1, p_h);
    k_agg<<<gAgg, TB>>>(p_h, out);
}

// round 9
// speedup vs baseline: 1.7236x; 1.0101x over previous
#include <cuda_runtime.h>
#include <cuda_fp16.h>
#include <cstdint>

// GCN 2-layer, CSR two-phase aggregation, sm_100a.
// Hs = dis*(X@W) stored fp16; agg uses 16 lanes/node (uint2 per edge per lane)
// for max warp parallelism at halved gather traffic; fp32 accumulation.

#define N_NODES 100000
#define N_EDGES 1600000
#define D 64
#define FIXS 33554432.0f          // 2^25 fixed-point scale for weight sums
#define FIXR (1.0f / 33554432.0f)

__device__ unsigned long long g_pk[N_NODES];  // (cnt << 32) | fixed_weight_sum
__device__ float g_dis[N_NODES];        // rsqrt(degree)
__device__ int   g_cnt[N_NODES];        // in-degree (edges only)
__device__ int   g_row[N_NODES];        // CSR row start (bump-allocated)
__device__ int   g_total;               // bump allocator
__device__ int   g_pos[N_EDGES];        // within-bin slot (from hist atomic)
__device__ int2  g_bins[N_EDGES];       // (src, w-as-int), dst-binned
__device__ uint2 g_h[N_NODES * 16];     // Hs fp16: 64 half = 16 uint2 per node
__device__ float g_agg[N_NODES * D];    // layer-1 output (fp32)

// ---------------------------------------------------------------------------
__global__ void k_init() {
    int i = blockIdx.x * blockDim.x + threadIdx.x;
    if (i < N_NODES) g_pk[i] = 0ULL;
    if (i == 0) g_total = 0;
}

// one packed 64-bit atomic per edge: count (hi) + fixed-point weight sum (lo)
__global__ void k_hist(const int* __restrict__ dst,
                       const float* __restrict__ w) {
    int t = blockIdx.x * blockDim.x + threadIdx.x;
    if (t >= N_EDGES / 4) return;
    int4   dv = ((const int4*)dst)[t];
    float4 wv = ((const float4*)w)[t];
    unsigned long long a0 = (1ULL << 32) | (unsigned)__float2uint_rn(wv.x * FIXS);
    unsigned long long a1 = (1ULL << 32) | (unsigned)__float2uint_rn(wv.y * FIXS);
    unsigned long long a2 = (1ULL << 32) | (unsigned)__float2uint_rn(wv.z * FIXS);
    unsigned long long a3 = (1ULL << 32) | (unsigned)__float2uint_rn(wv.w * FIXS);
    int p0 = (int)(atomicAdd(&g_pk[dv.x], a0) >> 32);
    int p1 = (int)(atomicAdd(&g_pk[dv.y], a1) >> 32);
    int p2 = (int)(atomicAdd(&g_pk[dv.z], a2) >> 32);
    int p3 = (int)(atomicAdd(&g_pk[dv.w], a3) >> 32);
    ((int4*)g_pos)[t] = make_int4(p0, p1, p2, p3);
}

__global__ void k_alloc() {
    int i = blockIdx.x * blockDim.x + threadIdx.x;
    if (i >= N_NODES) return;
    unsigned long long pk = g_pk[i];
    int cnt = (int)(pk >> 32);
    float deg = 1.0f + (float)(unsigned)(pk & 0xFFFFFFFFULL) * FIXR;
    g_dis[i] = rsqrtf(deg);
    g_cnt[i] = cnt;
    g_row[i] = atomicAdd(&g_total, cnt);
}

// fill bins: payload (src, raw w); one row[dst] gather, no dis gathers
__global__ void k_fill(const int* __restrict__ src,
                       const int* __restrict__ dst,
                       const float* __restrict__ w) {
    int t = blockIdx.x * blockDim.x + threadIdx.x;
    if (t >= N_EDGES / 4) return;
    int4   sv = ((const int4*)src)[t];
    int4   dv = ((const int4*)dst)[t];
    int4   pv = ((const int4*)g_pos)[t];
    float4 wv = ((const float4*)w)[t];
    int r0 = g_row[dv.x], r1 = g_row[dv.y], r2 = g_row[dv.z], r3 = g_row[dv.w];
    g_bins[r0 + pv.x] = make_int2(sv.x, __float_as_int(wv.x));
    g_bins[r1 + pv.y] = make_int2(sv.y, __float_as_int(wv.y));
    g_bins[r2 + pv.z] = make_int2(sv.z, __float_as_int(wv.z));
    g_bins[r3 + pv.w] = make_int2(sv.w, __float_as_int(wv.w));
}

// ---------------------------------------------------------------------------
// dense 64x64 GEMM, fp16 output: Hs[row] = half( dis[row] * (X[row] @ W) )
// ---------------------------------------------------------------------------
__global__ void __launch_bounds__(128) k_gemm(const float* __restrict__ X,
                                              const float* __restrict__ W,
                                              uint2* __restrict__ H) {
    __shared__ float Ws[D * D];
    int tid = threadIdx.x;
    {
        const float4* W4 = (const float4*)W;
        float4* Ws4 = (float4*)Ws;
#pragma unroll
        for (int i = 0; i < 8; ++i) Ws4[tid + i * 128] = W4[tid + i * 128];
    }
    __syncthreads();

    int row = blockIdx.x * 128 + tid;
    if (row >= N_NODES) return;

    float di = g_dis[row];
    const float4* x4 = (const float4*)(X + (size_t)row * D);

#pragma unroll 1
    for (int jc = 0; jc < 4; ++jc) {            // 16 output channels per chunk
        float acc[16];
#pragma unroll
        for (int j = 0; j < 16; ++j) acc[j] = 0.f;

#pragma unroll
        for (int k4 = 0; k4 < 16; ++k4) {
            float4 xv = x4[k4];
            float xs[4] = {xv.x, xv.y, xv.z, xv.w};
#pragma unroll
            for (int kk = 0; kk < 4; ++kk) {
                int k = k4 * 4 + kk;
                const float4* wrow = (const float4*)(Ws + k * D + jc * 16);
#pragma unroll
                for (int q = 0; q < 4; ++q) {
                    float4 wv = wrow[q];
                    acc[q * 4 + 0] = fmaf(xs[kk], wv.x, acc[q * 4 + 0]);
                    acc[q * 4 + 1] = fmaf(xs[kk], wv.y, acc[q * 4 + 1]);
                    acc[q * 4 + 2] = fmaf(xs[kk], wv.z, acc[q * 4 + 2]);
                    acc[q * 4 + 3] = fmaf(xs[kk], wv.w, acc[q * 4 + 3]);
                }
            }
        }
        // pack 16 fp32 -> 8 half2 -> 4 uint2 (channels 16*jc .. 16*jc+15)
#pragma unroll
        for (int q = 0; q < 4; ++q) {
            __half2 h0 = __floats2half2_rn(acc[q * 4 + 0] * di, acc[q * 4 + 1] * di);
            __half2 h1 = __floats2half2_rn(acc[q * 4 + 2] * di, acc[q * 4 + 3] * di);
            H[(size_t)row * 16 + jc * 4 + q] =
                make_uint2(*(unsigned*)&h0, *(unsigned*)&h1);
        }
    }
}

// ---------------------------------------------------------------------------
// CSR aggregate: 16 lanes per node; lane owns 4 channels (uint2 = 2 half2).
// fp32 accumulation; fused self-loop, dis scale, ReLU. x8 unroll (MLP=8).
// ---------------------------------------------------------------------------
__device__ __forceinline__ void acc_h4(float4& acc, uint2 v, float nm) {
    float2 f0 = __half22float2(*(__half2*)&v.x);
    float2 f1 = __half22float2(*(__half2*)&v.y);
    acc.x = fmaf(nm, f0.x, acc.x); acc.y = fmaf(nm, f0.y, acc.y);
    acc.z = fmaf(nm, f1.x, acc.z); acc.w = fmaf(nm, f1.y, acc.w);
}

__global__ void __launch_bounds__(256) k_agg(const uint2* __restrict__ H,
                                             float* __restrict__ A) {
    int idx = blockIdx.x * 256 + threadIdx.x;
    int n = idx >> 4;
    if (n >= N_NODES) return;
    int l = idx & 15;

    int e   = g_row[n];
    int end = e + g_cnt[n];

    float4 acc;
    {   // self-loop term Hs[n]
        uint2 sv = H[(size_t)n * 16 + l];
        float2 f0 = __half22float2(*(__half2*)&sv.x);
        float2 f1 = __half22float2(*(__half2*)&sv.y);
        acc = make_float4(f0.x, f0.y, f1.x, f1.y);
    }

    for (; e + 8 <= end; e += 8) {
        int2 p[8];
#pragma unroll
        for (int j = 0; j < 8; ++j) p[j] = g_bins[e + j];
        uint2 v[8];
#pragma unroll
        for (int j = 0; j < 8; ++j) v[j] = H[(size_t)p[j].x * 16 + l];
#pragma unroll
        for (int j = 0; j < 8; ++j) acc_h4(acc, v[j], __int_as_float(p[j].y));
    }
    if (e + 4 <= end) {
        int2 p[4];
#pragma unroll
        for (int j = 0; j < 4; ++j) p[j] = g_bins[e + j];
        uint2 v[4];
#pragma unroll
        for (int j = 0; j < 4; ++j) v[j] = H[(size_t)p[j].x * 16 + l];
#pragma unroll
        for (int j = 0; j < 4; ++j) acc_h4(acc, v[j], __int_as_float(p[j].y));
        e += 4;
    }
    for (; e < end; ++e) {
        int2 p = g_bins[e];
        uint2 v = H[(size_t)p.x * 16 + l];
        acc_h4(acc, v, __int_as_float(p.y));
    }

    float di = g_dis[n];
    acc.x = fmaxf(acc.x * di, 0.f); acc.y = fmaxf(acc.y * di, 0.f);
    acc.z = fmaxf(acc.z * di, 0.f); acc.w = fmaxf(acc.w * di, 0.f);
    ((float4*)A)[(size_t)n * 16 + l] = acc;
}

// ---------------------------------------------------------------------------
extern "C" void kernel_launch(void* const* d_in, const int* in_sizes, int n_in,
                              void* d_out, int out_size) {
    const float* x   = (const float*)d_in[0];
    const int*   ei  = (const int*)d_in[1];     // int32 (JAX x64 disabled)
    const float* w   = (const float*)d_in[2];
    const float* W0  = (const float*)d_in[3];
    const float* W1  = (const float*)d_in[4];
    float* out = (float*)d_out;

    const int* src = ei;
    const int* dst = ei + N_EDGES;

    uint2* p_h;
    float* p_agg;
    cudaGetSymbolAddress((void**)&p_h, g_h);
    cudaGetSymbolAddress((void**)&p_agg, g_agg);

    const int TB = 256;
    int gN    = (N_NODES + TB - 1) / TB;
    int gE4   = (N_EDGES / 4 + TB - 1) / TB;
    int gAgg  = (N_NODES * 16 + TB - 1) / TB;
    int gGemm = (N_NODES + 127) / 128;

    // prep
    k_init<<<gN, TB>>>();
    k_hist<<<gE4, TB>>>(dst, w);
    k_alloc<<<gN, TB>>>();
    k_fill<<<gE4, TB>>>(src, dst, w);

    // layer 1
    k_gemm<<<gGemm, 128>>>(x, W0, p_h);
    k_agg<<<gAgg, TB>>>(p_h, p_agg);

    // layer 2
    k_gemm<<<gGemm, 128>>>(p_agg, W1, p_h);
    k_agg<<<gAgg, TB>>>(p_h, out);
}

// round 11
// speedup vs baseline: 2.0371x; 1.1819x over previous
#include <cuda_runtime.h>
#include <cuda_fp16.h>
#include <cstdint>

// GCN 2-layer, CSR two-phase aggregation, sm_100a.
// GEMM uses Blackwell packed fma.rn.f32x2 (fp32 precision, half the FMA
// instructions) with 2 rows/thread (halves LDS instr). Hs stored fp16.

#define N_NODES 100000
#define N_EDGES 1600000
#define D 64
#define FIXS 33554432.0f          // 2^25 fixed-point scale for weight sums
#define FIXR (1.0f / 33554432.0f)

__device__ unsigned long long g_pk[N_NODES];  // (cnt << 32) | fixed_weight_sum
__device__ float g_dis[N_NODES];        // rsqrt(degree)
__device__ int   g_cnt[N_NODES];        // in-degree (edges only)
__device__ int   g_row[N_NODES];        // CSR row start (bump-allocated)
__device__ int   g_total;               // bump allocator
__device__ int   g_pos[N_EDGES];        // within-bin slot (from hist atomic)
__device__ int2  g_bins[N_EDGES];       // (src, w-as-int), dst-binned
__device__ uint2 g_h[N_NODES * 16];     // Hs fp16: 64 half = 16 uint2 per node
__device__ float g_agg[N_NODES * D];    // layer-1 output (fp32)

// ---------------------------------------------------------------------------
// packed f32x2 helpers (sm_100+)
// ---------------------------------------------------------------------------
__device__ __forceinline__ unsigned long long bcast2(float x) {
    unsigned long long r;
    asm("mov.b64 %0, {%1, %1};" : "=l"(r) : "f"(x));
    return r;
}
__device__ __forceinline__ void fma2(unsigned long long& d,
                                     unsigned long long a,
                                     unsigned long long b) {
    asm("fma.rn.f32x2 %0, %1, %2, %0;" : "+l"(d) : "l"(a), "l"(b));
}
__device__ __forceinline__ float2 unpack2(unsigned long long v) {
    float2 f;
    asm("mov.b64 {%0, %1}, %2;" : "=f"(f.x), "=f"(f.y) : "l"(v));
    return f;
}

// ---------------------------------------------------------------------------
__global__ void k_init() {
    int i = blockIdx.x * blockDim.x + threadIdx.x;
    if (i < N_NODES) g_pk[i] = 0ULL;
    if (i == 0) g_total = 0;
}

// one packed 64-bit atomic per edge: count (hi) + fixed-point weight sum (lo)
__global__ void k_hist(const int* __restrict__ dst,
                       const float* __restrict__ w) {
    int t = blockIdx.x * blockDim.x + threadIdx.x;
    if (t >= N_EDGES / 4) return;
    int4   dv = ((const int4*)dst)[t];
    float4 wv = ((const float4*)w)[t];
    unsigned long long a0 = (1ULL << 32) | (unsigned)__float2uint_rn(wv.x * FIXS);
    unsigned long long a1 = (1ULL << 32) | (unsigned)__float2uint_rn(wv.y * FIXS);
    unsigned long long a2 = (1ULL << 32) | (unsigned)__float2uint_rn(wv.z * FIXS);
    unsigned long long a3 = (1ULL << 32) | (unsigned)__float2uint_rn(wv.w * FIXS);
    int p0 = (int)(atomicAdd(&g_pk[dv.x], a0) >> 32);
    int p1 = (int)(atomicAdd(&g_pk[dv.y], a1) >> 32);
    int p2 = (int)(atomicAdd(&g_pk[dv.z], a2) >> 32);
    int p3 = (int)(atomicAdd(&g_pk[dv.w], a3) >> 32);
    ((int4*)g_pos)[t] = make_int4(p0, p1, p2, p3);
}

__global__ void k_alloc() {
    int i = blockIdx.x * blockDim.x + threadIdx.x;
    if (i >= N_NODES) return;
    unsigned long long pk = g_pk[i];
    int cnt = (int)(pk >> 32);
    float deg = 1.0f + (float)(unsigned)(pk & 0xFFFFFFFFULL) * FIXR;
    g_dis[i] = rsqrtf(deg);
    g_cnt[i] = cnt;
    g_row[i] = atomicAdd(&g_total, cnt);
}

// fill bins: payload (src, raw w); one row[dst] gather, no dis gathers
__global__ void k_fill(const int* __restrict__ src,
                       const int* __restrict__ dst,
                       const float* __restrict__ w) {
    int t = blockIdx.x * blockDim.x + threadIdx.x;
    if (t >= N_EDGES / 4) return;
    int4   sv = ((const int4*)src)[t];
    int4   dv = ((const int4*)dst)[t];
    int4   pv = ((const int4*)g_pos)[t];
    float4 wv = ((const float4*)w)[t];
    int r0 = g_row[dv.x], r1 = g_row[dv.y], r2 = g_row[dv.z], r3 = g_row[dv.w];
    g_bins[r0 + pv.x] = make_int2(sv.x, __float_as_int(wv.x));
    g_bins[r1 + pv.y] = make_int2(sv.y, __float_as_int(wv.y));
    g_bins[r2 + pv.z] = make_int2(sv.z, __float_as_int(wv.z));
    g_bins[r3 + pv.w] = make_int2(sv.w, __float_as_int(wv.w));
}

// ---------------------------------------------------------------------------
// dense 64x64 GEMM, f32x2 packed math, 2 rows/thread, fp16 output:
//   Hs[row] = half( dis[row] * (X[row] @ W) )
// ---------------------------------------------------------------------------
__global__ void __launch_bounds__(128) k_gemm(const float* __restrict__ X,
                                              const float* __restrict__ W,
                                              uint2* __restrict__ H) {
    __shared__ ulonglong2 WsU[1024];          // 64x64 floats = 16KB = 1024x16B
    float* Ws = (float*)WsU;
    int tid = threadIdx.x;
    {
        const float4* W4 = (const float4*)W;
        float4* Ws4 = (float4*)Ws;
#pragma unroll
        for (int i = 0; i < 8; ++i) Ws4[tid + i * 128] = W4[tid + i * 128];
    }
    __syncthreads();

    int r0 = blockIdx.x * 256 + tid;
    int r1 = r0 + 128;
    bool has0 = (r0 < N_NODES), has1 = (r1 < N_NODES);
    if (!has0) return;

    float di0 = g_dis[r0];
    float di1 = has1 ? g_dis[r1] : 0.f;
    const float4* x0 = (const float4*)(X + (size_t)r0 * D);
    const float4* x1 = (const float4*)(X + (size_t)(has1 ? r1 : r0) * D);

#pragma unroll 1
    for (int jc = 0; jc < 4; ++jc) {            // 16 output channels per chunk
        unsigned long long a0[8], a1[8];
#pragma unroll
        for (int j = 0; j < 8; ++j) { a0[j] = 0ULL; a1[j] = 0ULL; }

#pragma unroll
        for (int k4 = 0; k4 < 16; ++k4) {
            float4 xv0 = x0[k4];
            float4 xv1 = x1[k4];
            float xs0[4] = {xv0.x, xv0.y, xv0.z, xv0.w};
            float xs1[4] = {xv1.x, xv1.y, xv1.z, xv1.w};
#pragma unroll
            for (int kk = 0; kk < 4; ++kk) {
                int k = k4 * 4 + kk;
                unsigned long long xb0 = bcast2(xs0[kk]);
                unsigned long long xb1 = bcast2(xs1[kk]);
                const ulonglong2* wrow =
                    (const ulonglong2*)(Ws + k * D + jc * 16);
#pragma unroll
                for (int q = 0; q < 4; ++q) {
                    ulonglong2 wp = wrow[q];     // LDS.128 = 2 packed pairs
                    fma2(a0[q * 2 + 0], wp.x, xb0);
                    fma2(a0[q * 2 + 1], wp.y, xb0);
                    fma2(a1[q * 2 + 0], wp.x, xb1);
                    fma2(a1[q * 2 + 1], wp.y, xb1);
                }
            }
        }
        // unpack, scale, convert to fp16, store (4 uint2 per row per chunk)
#pragma unroll
        for (int q = 0; q < 4; ++q) {
            float2 f0 = unpack2(a0[q * 2 + 0]);
            float2 f1 = unpack2(a0[q * 2 + 1]);
            __half2 h0 = __floats2half2_rn(f0.x * di0, f0.y * di0);
            __half2 h1 = __floats2half2_rn(f1.x * di0, f1.y * di0);
            H[(size_t)r0 * 16 + jc * 4 + q] =
                make_uint2(*(unsigned*)&h0, *(unsigned*)&h1);
        }
        if (has1) {
#pragma unroll
            for (int q = 0; q < 4; ++q) {
                float2 f0 = unpack2(a1[q * 2 + 0]);
                float2 f1 = unpack2(a1[q * 2 + 1]);
                __half2 h0 = __floats2half2_rn(f0.x * di1, f0.y * di1);
                __half2 h1 = __floats2half2_rn(f1.x * di1, f1.y * di1);
                H[(size_t)r1 * 16 + jc * 4 + q] =
                    make_uint2(*(unsigned*)&h0, *(unsigned*)&h1);
            }
        }
    }
}

// ---------------------------------------------------------------------------
// CSR aggregate: 16 lanes per node; lane owns 4 channels (uint2 = 2 half2).
// fp32 accumulation; fused self-loop, dis scale, ReLU. x8 unroll (MLP=8).
// ---------------------------------------------------------------------------
__device__ __forceinline__ void acc_h4(float4& acc, uint2 v, float nm) {
    float2 f0 = __half22float2(*(__half2*)&v.x);
    float2 f1 = __half22float2(*(__half2*)&v.y);
    acc.x = fmaf(nm, f0.x, acc.x); acc.y = fmaf(nm, f0.y, acc.y);
    acc.z = fmaf(nm, f1.x, acc.z); acc.w = fmaf(nm, f1.y, acc.w);
}

__global__ void __launch_bounds__(256) k_agg(const uint2* __restrict__ H,
                                             float* __restrict__ A) {
    int idx = blockIdx.x * 256 + threadIdx.x;
    int n = idx >> 4;
    if (n >= N_NODES) return;
    int l = idx & 15;

    int e   = g_row[n];
    int end = e + g_cnt[n];

    float4 acc;
    {   // self-loop term Hs[n]
        uint2 sv = H[(size_t)n * 16 + l];
        float2 f0 = __half22float2(*(__half2*)&sv.x);
        float2 f1 = __half22float2(*(__half2*)&sv.y);
        acc = make_float4(f0.x, f0.y, f1.x, f1.y);
    }

    for (; e + 8 <= end; e += 8) {
        int2 p[8];
#pragma unroll
        for (int j = 0; j < 8; ++j) p[j] = g_bins[e + j];
        uint2 v[8];
#pragma unroll
        for (int j = 0; j < 8; ++j) v[j] = H[(size_t)p[j].x * 16 + l];
#pragma unroll
        for (int j = 0; j < 8; ++j) acc_h4(acc, v[j], __int_as_float(p[j].y));
    }
    if (e + 4 <= end) {
        int2 p[4];
#pragma unroll
        for (int j = 0; j < 4; ++j) p[j] = g_bins[e + j];
        uint2 v[4];
#pragma unroll
        for (int j = 0; j < 4; ++j) v[j] = H[(size_t)p[j].x * 16 + l];
#pragma unroll
        for (int j = 0; j < 4; ++j) acc_h4(acc, v[j], __int_as_float(p[j].y));
        e += 4;
    }
    for (; e < end; ++e) {
        int2 p = g_bins[e];
        uint2 v = H[(size_t)p.x * 16 + l];
        acc_h4(acc, v, __int_as_float(p.y));
    }

    float di = g_dis[n];
    acc.x = fmaxf(acc.x * di, 0.f); acc.y = fmaxf(acc.y * di, 0.f);
    acc.z = fmaxf(acc.z * di, 0.f); acc.w = fmaxf(acc.w * di, 0.f);
    ((float4*)A)[(size_t)n * 16 + l] = acc;
}

// ---------------------------------------------------------------------------
extern "C" void kernel_launch(void* const* d_in, const int* in_sizes, int n_in,
                              void* d_out, int out_size) {
    const float* x   = (const float*)d_in[0];
    const int*   ei  = (const int*)d_in[1];     // int32 (JAX x64 disabled)
    const float* w   = (const float*)d_in[2];
    const float* W0  = (const float*)d_in[3];
    const float* W1  = (const float*)d_in[4];
    float* out = (float*)d_out;

    const int* src = ei;
    const int* dst = ei + N_EDGES;

    uint2* p_h;
    float* p_agg;
    cudaGetSymbolAddress((void**)&p_h, g_h);
    cudaGetSymbolAddress((void**)&p_agg, g_agg);

    const int TB = 256;
    int gN    = (N_NODES + TB - 1) / TB;
    int gE4   = (N_EDGES / 4 + TB - 1) / TB;
    int gAgg  = (N_NODES * 16 + TB - 1) / TB;
    int gGemm = (N_NODES + 255) / 256;          // 2 rows/thread, 128 thr

    // prep
    k_init<<<gN, TB>>>();
    k_hist<<<gE4, TB>>>(dst, w);
    k_alloc<<<gN, TB>>>();
    k_fill<<<gE4, TB>>>(src, dst, w);

    // layer 1
    k_gemm<<<gGemm, 128>>>(x, W0, p_h);
    k_agg<<<gAgg, TB>>>(p_h, p_agg);

    // layer 2
    k_gemm<<<gGemm, 128>>>(p_agg, W1, p_h);
    k_agg<<<gAgg, TB>>>(p_h, out);
}